// round 8
// baseline (speedup 1.0000x reference)
#include <cuda_runtime.h>
#include <cuda_bf16.h>
#include <math.h>
#include <stdint.h>

#define NTOK   131072
#define DIM    256
#define NCODE  1024
#define ND     (NTOK*DIM)

// smem: A = 128 tok x 256 int8 = 32KB ; B = 2 x (128 codes x 256 int8) = 64KB
#define SMEM_A_BYTES   32768
#define SMEM_B_STAGE   32768
#define SMEM_TOTAL     (SMEM_A_BYTES + 2*SMEM_B_STAGE)   // 98304

// ---------------- persistent device scratch ----------------
__device__ float          g_cn[NCODE*DIM];      // normalized codebook fp32
__device__ int8_t         g_cb_i8[NCODE*DIM];   // int8 codebook (global scale)
__device__ unsigned int   g_cmax;               // max |cn| as float bits
__device__ int4           g_cand[NTOK];         // top-4 candidates per token
__device__ unsigned int   g_counts[NCODE];
__device__ double         g_sumsq;

__device__ __forceinline__ uint32_t smem_u32(const void* p) {
    uint32_t a;
    asm("{ .reg .u64 t; cvta.to.shared.u64 t, %1; cvt.u32.u64 %0, t; }" : "=r"(a) : "l"(p));
    return a;
}

#define LDSM4(r0,r1,r2,r3,a) \
    asm volatile("ldmatrix.sync.aligned.m8n8.x4.shared.b16 {%0,%1,%2,%3}, [%4];" \
        : "=r"(r0),"=r"(r1),"=r"(r2),"=r"(r3) : "r"(a))

#define MMAI8(d,a0,a1,a2,a3,b0,b1) \
    asm volatile("mma.sync.aligned.m16n8k32.row.col.s32.s8.s8.s32 " \
        "{%0,%1,%2,%3},{%4,%5,%6,%7},{%8,%9},{%0,%1,%2,%3};" \
        : "+r"((d)[0]),"+r"((d)[1]),"+r"((d)[2]),"+r"((d)[3]) \
        : "r"(a0),"r"(a1),"r"(a2),"r"(a3),"r"(b0),"r"(b1))

#define CP_ASYNC16(dst, src) \
    asm volatile("cp.async.cg.shared.global [%0], [%1], 16;" :: "r"(dst), "l"(src))
#define CP_COMMIT() asm volatile("cp.async.commit_group;" ::: "memory")
#define CP_WAIT0()  asm volatile("cp.async.wait_group 0;"  ::: "memory")

__device__ __forceinline__ uint32_t pack4(float a, float b, float c, float d, float inv) {
    int q0 = __float2int_rn(a*inv), q1 = __float2int_rn(b*inv);
    int q2 = __float2int_rn(c*inv), q3 = __float2int_rn(d*inv);
    return (uint32_t)(q0 & 0xff) | ((uint32_t)(q1 & 0xff) << 8) |
           ((uint32_t)(q2 & 0xff) << 16) | ((uint32_t)(q3 & 0xff) << 24);
}

// ============================================================
__global__ void k_init() {
    int t = threadIdx.x;
    if (t < NCODE) g_counts[t] = 0u;
    if (t == 0) { g_sumsq = 0.0; g_cmax = 0u; }
}

// ============================================================
// normalize codebook; record global max |cn|
// ============================================================
__global__ void k_norm(const float* __restrict__ w) {
    int row = blockIdx.x;
    int t   = threadIdx.x;                       // 64 threads
    float4 v = ((const float4*)(w + row*DIM))[t];
    float s  = v.x*v.x + v.y*v.y + v.z*v.z + v.w*v.w;
    #pragma unroll
    for (int o = 16; o > 0; o >>= 1) s += __shfl_xor_sync(0xffffffffu, s, o);
    __shared__ float ss[2];
    if ((t & 31) == 0) ss[t >> 5] = s;
    __syncthreads();
    float n = sqrtf(ss[0] + ss[1]);
    float r = 1.0f / fmaxf(n, 1e-12f);
    float c[4] = { v.x*r, v.y*r, v.z*r, v.w*r };
    ((float4*)(g_cn + row*DIM))[t] = make_float4(c[0], c[1], c[2], c[3]);
    float am = fmaxf(fmaxf(fabsf(c[0]), fabsf(c[1])), fmaxf(fabsf(c[2]), fabsf(c[3])));
    #pragma unroll
    for (int o = 16; o > 0; o >>= 1) am = fmaxf(am, __shfl_xor_sync(0xffffffffu, am, o));
    if ((t & 31) == 0) atomicMax(&g_cmax, __float_as_uint(am));
}

// ============================================================
// quantize codebook to int8 with global scale
// ============================================================
__global__ void k_quantc() {
    int row = blockIdx.x, t = threadIdx.x;       // 64 threads
    float cmax = __uint_as_float(g_cmax);
    float inv  = (cmax > 0.f) ? 127.0f / cmax : 0.f;
    float4 v = ((const float4*)(g_cn + row*DIM))[t];
    ((uint32_t*)(g_cb_i8 + row*DIM))[t] = pack4(v.x, v.y, v.z, v.w, inv);
}

// ============================================================
// int8 IMMA GEMM + streaming per-thread top-3 -> token top-4.
// CTA: 128 tokens, 8 warps (4m x 2n). 8 N-tile stages of K=256,
// B double-buffered (32KB stages) via cp.async. 2 CTAs/SM.
// ============================================================
__global__ void __launch_bounds__(256, 2)
k_gemm(const float* __restrict__ z) {
    extern __shared__ char sm[];
    char* As = sm;
    const uint32_t sb = smem_u32(sm);

    const int tid  = threadIdx.x;
    const int wid  = tid >> 5, lane = tid & 31;
    const int wm   = wid & 3,  wn   = wid >> 2;
    const int mBase = blockIdx.x * 128;

    // ---- A fill: per-token max-abs scale, quantize to int8, swizzled ----
    {
        #pragma unroll 1
        for (int i = 0; i < 16; i++) {
            int tok = wid*16 + i;
            const float4* zrow = (const float4*)(z + (size_t)(mBase + tok)*DIM);
            float4 va = zrow[lane];
            float4 vb = zrow[lane + 32];
            float m = fmaxf(fmaxf(fabsf(va.x), fabsf(va.y)), fmaxf(fabsf(va.z), fabsf(va.w)));
            m = fmaxf(m, fmaxf(fmaxf(fabsf(vb.x), fabsf(vb.y)), fmaxf(fabsf(vb.z), fabsf(vb.w))));
            #pragma unroll
            for (int o = 16; o > 0; o >>= 1) m = fmaxf(m, __shfl_xor_sync(0xffffffffu, m, o));
            float inv = (m > 0.f) ? 127.0f / m : 0.f;
            uint32_t u0 = pack4(va.x, va.y, va.z, va.w, inv);
            uint32_t u1 = pack4(vb.x, vb.y, vb.z, vb.w, inv);
            int base = tok*256, xo = (tok & 7)*16;
            *(uint32_t*)(As + base + ((lane*4)       ^ xo)) = u0;
            *(uint32_t*)(As + base + ((128 + lane*4) ^ xo)) = u1;
        }
    }

    // ---- B cp.async addressing: stage = 128 rows x 256B, 16B chunks ----
    const int r0 = tid >> 4, gr = tid & 15;
    const uint32_t bdst0 = sb + SMEM_A_BYTES +
        (uint32_t)(r0*256 + ((gr*16) ^ ((r0 & 7)*16)));
    const char* bsrc0 = (const char*)g_cb_i8 + (size_t)r0*256 + gr*16;

    // prologue: issue stage 0
    #pragma unroll
    for (int j = 0; j < 8; j++)
        CP_ASYNC16(bdst0 + j*4096u, bsrc0 + (size_t)j*4096);
    CP_COMMIT();

    // ---- per-lane ldmatrix address components ----
    const int lr  = lane & 7;
    const int l8  = (lane >> 3) & 1;
    const int l16 = (lane >> 4) & 1;
    const uint32_t aBase = sb + (uint32_t)(wm*32 + lr + l8*8) * 256;
    const uint32_t kaddA = (uint32_t)(l16 * 16);
    const uint32_t bBase = sb + SMEM_A_BYTES + (uint32_t)(wn*64 + l16*8 + lr) * 256;
    const uint32_t kaddB = (uint32_t)(l8 * 16);
    const uint32_t lXor  = (uint32_t)(lr * 16);

    int acc[64];
    #pragma unroll
    for (int i = 0; i < 64; i++) acc[i] = 0;

    int v1[4], v2[4], v3[4], i1[4], i2[4], i3[4];
    #pragma unroll
    for (int s = 0; s < 4; s++) {
        v1[s] = v2[s] = v3[s] = -2147483647;
        i1[s] = i2[s] = i3[s] = 0;
    }

    #pragma unroll 1
    for (int nt = 0; nt < 8; nt++) {
        CP_WAIT0();
        __syncthreads();

        // issue next stage into the other buffer (prev compute done by sync)
        if (nt + 1 < 8) {
            uint32_t dst = bdst0 + (uint32_t)((nt + 1) & 1)*SMEM_B_STAGE;
            const char* src = bsrc0 + (size_t)(nt + 1)*32768;
            #pragma unroll
            for (int j = 0; j < 8; j++)
                CP_ASYNC16(dst + j*4096u, src + (size_t)j*4096);
            CP_COMMIT();
        }

        // ---- compute this N-tile: 8 k32-steps ----
        {
            const uint32_t bufB = (uint32_t)(nt & 1)*SMEM_B_STAGE;
            #pragma unroll
            for (int kk = 0; kk < 8; kk++) {
                uint32_t kb = (uint32_t)(kk*32);
                uint32_t aAddr = aBase + ((kb + kaddA) ^ lXor);
                uint32_t a0[4], a1[4];
                LDSM4(a0[0], a0[1], a0[2], a0[3], aAddr);
                LDSM4(a1[0], a1[1], a1[2], a1[3], aAddr + 4096);

                uint32_t bAddr = bBase + bufB + ((kb + kaddB) ^ lXor);
                #pragma unroll
                for (int gb = 0; gb < 2; gb++) {
                    uint32_t bf[8];
                    LDSM4(bf[0], bf[1], bf[2], bf[3], bAddr + (uint32_t)(2*gb)*4096);
                    LDSM4(bf[4], bf[5], bf[6], bf[7], bAddr + (uint32_t)(2*gb+1)*4096);
                    #pragma unroll
                    for (int tt = 0; tt < 4; tt++) {
                        int t8 = gb*4 + tt;
                        uint32_t b0 = bf[(tt >> 1)*4 + (tt & 1)*2 + 0];
                        uint32_t b1 = bf[(tt >> 1)*4 + (tt & 1)*2 + 1];
                        MMAI8(&acc[t8*4],      a0[0], a0[1], a0[2], a0[3], b0, b1);
                        MMAI8(&acc[32 + t8*4], a1[0], a1[1], a1[2], a1[3], b0, b1);
                    }
                }
            }
        }

        // ---- fold this N-tile into per-thread top-3, reset acc ----
        {
            int cBase = nt*128 + wn*64 + (lane & 3)*2;
            #pragma unroll
            for (int mt = 0; mt < 2; mt++) {
                #pragma unroll
                for (int rg = 0; rg < 2; rg++) {
                    int s = mt*2 + rg;
                    #pragma unroll
                    for (int t8 = 0; t8 < 8; t8++) {
                        #pragma unroll
                        for (int e = 0; e < 2; e++) {
                            int v = acc[mt*32 + t8*4 + rg*2 + e];
                            int code = cBase + t8*8 + e;
                            if (v > v1[s]) {
                                v3[s]=v2[s]; i3[s]=i2[s];
                                v2[s]=v1[s]; i2[s]=i1[s];
                                v1[s]=v;     i1[s]=code;
                            } else if (v > v2[s]) {
                                v3[s]=v2[s]; i3[s]=i2[s];
                                v2[s]=v;     i2[s]=code;
                            } else if (v > v3[s]) {
                                v3[s]=v;     i3[s]=code;
                            }
                        }
                    }
                }
            }
            #pragma unroll
            for (int i = 0; i < 64; i++) acc[i] = 0;
        }
    }

    // ---- dump per-thread top-3 to smem, merge to token top-4 ----
    __syncthreads();
    int2* red = (int2*)sm;                       // [128 tok][8 q][3]
    {
        int q = wn*4 + (lane & 3);
        int row = lane >> 2;
        #pragma unroll
        for (int mt = 0; mt < 2; mt++)
            #pragma unroll
            for (int rg = 0; rg < 2; rg++) {
                int s  = mt*2 + rg;
                int tl = wm*32 + mt*16 + rg*8 + row;
                int2* e = red + (tl*8 + q)*3;
                e[0] = make_int2(v1[s], i1[s]);
                e[1] = make_int2(v2[s], i2[s]);
                e[2] = make_int2(v3[s], i3[s]);
            }
    }
    __syncthreads();
    if (tid < 128) {
        int t1=-2147483647, t2=t1, t3=t1, t4=t1;
        int c1=0, c2=0, c3=0, c4=0;
        const int2* e = red + tid*24;
        #pragma unroll 4
        for (int j = 0; j < 24; j++) {
            int v = e[j].x, cd = e[j].y;
            if (v > t1)      { t4=t3;c4=c3; t3=t2;c3=c2; t2=t1;c2=c1; t1=v;c1=cd; }
            else if (v > t2) { t4=t3;c4=c3; t3=t2;c3=c2; t2=v;c2=cd; }
            else if (v > t3) { t4=t3;c4=c3; t3=v;c3=cd; }
            else if (v > t4) { t4=v;c4=cd; }
        }
        g_cand[mBase + tid] = make_int4(c1, c2, c3, c4);
    }
}

// ============================================================
// fp32 rescore of 4 candidates + gather z_q + loss + counts
// ============================================================
__global__ void k_fin(const float* __restrict__ z, const float* __restrict__ w,
                      float* __restrict__ out) {
    int wp = threadIdx.x >> 5, lane = threadIdx.x & 31;
    int token = blockIdx.x*8 + wp;
    int4 cd = g_cand[token];
    int cand[4] = { cd.x, cd.y, cd.z, cd.w };

    const float4* zz = (const float4*)(z + (size_t)token*DIM);
    const float4* pc[4];
    #pragma unroll
    for (int q = 0; q < 4; q++) pc[q] = (const float4*)(g_cn + (size_t)cand[q]*DIM);

    float4 zv[2];
    float d[4] = { 0.f, 0.f, 0.f, 0.f };
    #pragma unroll
    for (int rr = 0; rr < 2; rr++) {
        int j = lane + rr*32;
        zv[rr] = zz[j];
        #pragma unroll
        for (int q = 0; q < 4; q++) {
            float4 a = pc[q][j];
            d[q] += zv[rr].x*a.x + zv[rr].y*a.y + zv[rr].z*a.z + zv[rr].w*a.w;
        }
    }
    #pragma unroll
    for (int o = 16; o > 0; o >>= 1)
        #pragma unroll
        for (int q = 0; q < 4; q++)
            d[q] += __shfl_xor_sync(0xffffffffu, d[q], o);

    float bd = -3.4e38f; int win = 0x7fffffff;
    #pragma unroll
    for (int q = 0; q < 4; q++)
        if (d[q] > bd || (d[q] == bd && cand[q] < win)) { bd = d[q]; win = cand[q]; }

    const float4* e  = (const float4*)(w + (size_t)win*DIM);
    float4*       o4 = (float4*)(out + (size_t)token*DIM);
    float s = 0.f;
    #pragma unroll
    for (int rr = 0; rr < 2; rr++) {
        int j = lane + rr*32;
        float4 ev = e[j];
        o4[j] = ev;
        float dx = ev.x - zv[rr].x, dy = ev.y - zv[rr].y;
        float dz = ev.z - zv[rr].z, dw = ev.w - zv[rr].w;
        s += dx*dx + dy*dy + dz*dz + dw*dw;
    }
    #pragma unroll
    for (int o = 16; o > 0; o >>= 1) s += __shfl_xor_sync(0xffffffffu, s, o);
    if (lane == 0) {
        out[ND + 2 + token] = (float)win;
        atomicAdd(&g_counts[win], 1u);
    }
    __shared__ float ps[8];
    if (lane == 0) ps[wp] = s;
    __syncthreads();
    if (threadIdx.x == 0) {
        float tot = 0.f;
        #pragma unroll
        for (int i = 0; i < 8; i++) tot += ps[i];
        atomicAdd(&g_sumsq, (double)tot);
    }
}

// ============================================================
__global__ void k_final(float* __restrict__ out) {
    int t = threadIdx.x;                         // 1024 threads
    float p    = (float)g_counts[t] / (float)NTOK;
    float term = p * logf(p + 1e-10f);
    #pragma unroll
    for (int o = 16; o > 0; o >>= 1) term += __shfl_xor_sync(0xffffffffu, term, o);
    __shared__ float ws[32];
    if ((t & 31) == 0) ws[t >> 5] = term;
    __syncthreads();
    if (t < 32) {
        float v = ws[t];
        #pragma unroll
        for (int o = 16; o > 0; o >>= 1) v += __shfl_xor_sync(0xffffffffu, v, o);
        if (t == 0) {
            out[ND]     = (float)(1.25 * (g_sumsq / (double)ND));
            out[ND + 1] = expf(-v);
        }
    }
}

// ============================================================
extern "C" void kernel_launch(void* const* d_in, const int* in_sizes, int n_in,
                              void* d_out, int out_size) {
    const float* z = (const float*)d_in[0];      // [131072, 256]
    const float* w = (const float*)d_in[1];      // [1024, 256]
    float* out = (float*)d_out;

    cudaFuncSetAttribute(k_gemm, cudaFuncAttributeMaxDynamicSharedMemorySize, SMEM_TOTAL);

    k_init  <<<1, 1024>>>();
    k_norm  <<<NCODE, 64>>>(w);
    k_quantc<<<NCODE, 64>>>();
    k_gemm  <<<NTOK/128, 256, SMEM_TOTAL>>>(z);
    k_fin   <<<NTOK/8, 256>>>(z, w, out);
    k_final <<<1, 1024>>>(out);
}

// round 10
// speedup vs baseline: 1.2688x; 1.2688x over previous
#include <cuda_runtime.h>
#include <cuda_bf16.h>
#include <math.h>
#include <stdint.h>

#define NTOK   131072
#define DIM    256
#define NCODE  1024
#define ND     (NTOK*DIM)

// smem: A = 128 tok x 256 fp8 = 32KB ; B = 2 x (128 codes x 256 fp8) = 64KB
#define SMEM_A_BYTES   32768
#define SMEM_B_STAGE   32768
#define SMEM_TOTAL     (SMEM_A_BYTES + 2*SMEM_B_STAGE)   // 98304

#define NCAND  10

// ---------------- persistent device scratch ----------------
__device__ float          g_cn[NCODE*DIM];      // normalized codebook fp32
__device__ uint8_t        g_cb_f8[NCODE*DIM];   // e4m3 codebook (global scale)
__device__ unsigned int   g_cmax;               // max |cn| as float bits
__device__ int            g_cand[NTOK*NCAND];   // top-10 candidate codes per token
__device__ unsigned int   g_counts[NCODE];
__device__ double         g_sumsq;

__device__ __forceinline__ uint32_t smem_u32(const void* p) {
    uint32_t a;
    asm("{ .reg .u64 t; cvta.to.shared.u64 t, %1; cvt.u32.u64 %0, t; }" : "=r"(a) : "l"(p));
    return a;
}

// monotonic float -> uint transform, then pack 10-bit code into low bits
__device__ __forceinline__ uint32_t pack_sc(float f, int code) {
    uint32_t u = __float_as_uint(f);
    u = (u & 0x80000000u) ? ~u : (u | 0x80000000u);
    return (u & 0xFFFFFC00u) | (uint32_t)code;
}

#define LDSM4(r0,r1,r2,r3,a) \
    asm volatile("ldmatrix.sync.aligned.m8n8.x4.shared.b16 {%0,%1,%2,%3}, [%4];" \
        : "=r"(r0),"=r"(r1),"=r"(r2),"=r"(r3) : "r"(a))

#define MMAF8(d,a0,a1,a2,a3,b0,b1) \
    asm volatile("mma.sync.aligned.m16n8k32.row.col.f32.e4m3.e4m3.f32 " \
        "{%0,%1,%2,%3},{%4,%5,%6,%7},{%8,%9},{%0,%1,%2,%3};" \
        : "+f"((d)[0]),"+f"((d)[1]),"+f"((d)[2]),"+f"((d)[3]) \
        : "r"(a0),"r"(a1),"r"(a2),"r"(a3),"r"(b0),"r"(b1))

#define CP_ASYNC16(dst, src) \
    asm volatile("cp.async.cg.shared.global [%0], [%1], 16;" :: "r"(dst), "l"(src))
#define CP_COMMIT() asm volatile("cp.async.commit_group;" ::: "memory")
#define CP_WAIT0()  asm volatile("cp.async.wait_group 0;"  ::: "memory")

// pack 4 scaled floats into 4 e4m3 bytes (a in low byte)
__device__ __forceinline__ uint32_t pack4_e4m3(float a, float b, float c, float d, float s) {
    uint16_t lo, hi;
    float a_s = a*s, b_s = b*s, c_s = c*s, d_s = d*s;
    asm("cvt.rn.satfinite.e4m3x2.f32 %0, %1, %2;" : "=h"(lo) : "f"(b_s), "f"(a_s));
    asm("cvt.rn.satfinite.e4m3x2.f32 %0, %1, %2;" : "=h"(hi) : "f"(d_s), "f"(c_s));
    return (uint32_t)lo | ((uint32_t)hi << 16);
}

// ============================================================
__global__ void k_init() {
    int t = threadIdx.x;
    if (t < NCODE) g_counts[t] = 0u;
    if (t == 0) { g_sumsq = 0.0; g_cmax = 0u; }
}

// ============================================================
__global__ void k_norm(const float* __restrict__ w) {
    int row = blockIdx.x;
    int t   = threadIdx.x;                       // 64 threads
    float4 v = ((const float4*)(w + row*DIM))[t];
    float s  = v.x*v.x + v.y*v.y + v.z*v.z + v.w*v.w;
    #pragma unroll
    for (int o = 16; o > 0; o >>= 1) s += __shfl_xor_sync(0xffffffffu, s, o);
    __shared__ float ss[2];
    if ((t & 31) == 0) ss[t >> 5] = s;
    __syncthreads();
    float n = sqrtf(ss[0] + ss[1]);
    float r = 1.0f / fmaxf(n, 1e-12f);
    float c[4] = { v.x*r, v.y*r, v.z*r, v.w*r };
    ((float4*)(g_cn + row*DIM))[t] = make_float4(c[0], c[1], c[2], c[3]);
    float am = fmaxf(fmaxf(fabsf(c[0]), fabsf(c[1])), fmaxf(fabsf(c[2]), fabsf(c[3])));
    #pragma unroll
    for (int o = 16; o > 0; o >>= 1) am = fmaxf(am, __shfl_xor_sync(0xffffffffu, am, o));
    if ((t & 31) == 0) atomicMax(&g_cmax, __float_as_uint(am));
}

// ============================================================
__global__ void k_quantc() {
    int row = blockIdx.x, t = threadIdx.x;       // 64 threads
    float cmax = __uint_as_float(g_cmax);
    float s    = (cmax > 0.f) ? 448.0f / cmax : 0.f;
    float4 v = ((const float4*)(g_cn + row*DIM))[t];
    ((uint32_t*)(g_cb_f8 + row*DIM))[t] = pack4_e4m3(v.x, v.y, v.z, v.w, s);
}

// ============================================================
// fp8 e4m3 mma.sync GEMM + per-thread top-5 (packed) ->
// token top-10 candidates. CTA: 128 tokens, 8 warps (4m x 2n).
// ============================================================
__global__ void __launch_bounds__(256, 2)
k_gemm(const float* __restrict__ z) {
    extern __shared__ char sm[];
    char* As = sm;
    const uint32_t sb = smem_u32(sm);

    const int tid  = threadIdx.x;
    const int wid  = tid >> 5, lane = tid & 31;
    const int wm   = wid & 3,  wn   = wid >> 2;
    const int mBase = blockIdx.x * 128;

    // ---- A fill: per-token max-abs scale, quantize to e4m3, swizzled ----
    {
        #pragma unroll 1
        for (int i = 0; i < 16; i++) {
            int tok = wid*16 + i;
            const float4* zrow = (const float4*)(z + (size_t)(mBase + tok)*DIM);
            float4 va = zrow[lane];
            float4 vb = zrow[lane + 32];
            float m = fmaxf(fmaxf(fabsf(va.x), fabsf(va.y)), fmaxf(fabsf(va.z), fabsf(va.w)));
            m = fmaxf(m, fmaxf(fmaxf(fabsf(vb.x), fabsf(vb.y)), fmaxf(fabsf(vb.z), fabsf(vb.w))));
            #pragma unroll
            for (int o = 16; o > 0; o >>= 1) m = fmaxf(m, __shfl_xor_sync(0xffffffffu, m, o));
            float s = (m > 0.f) ? 448.0f / m : 0.f;
            uint32_t u0 = pack4_e4m3(va.x, va.y, va.z, va.w, s);
            uint32_t u1 = pack4_e4m3(vb.x, vb.y, vb.z, vb.w, s);
            int base = tok*256, xo = (tok & 7)*16;
            *(uint32_t*)(As + base + ((lane*4)       ^ xo)) = u0;
            *(uint32_t*)(As + base + ((128 + lane*4) ^ xo)) = u1;
        }
    }

    // ---- B cp.async addressing: stage = 128 rows x 256B, 16B chunks ----
    const int r0 = tid >> 4, gr = tid & 15;
    const uint32_t bdst0 = sb + SMEM_A_BYTES +
        (uint32_t)(r0*256 + ((gr*16) ^ ((r0 & 7)*16)));
    const char* bsrc0 = (const char*)g_cb_f8 + (size_t)r0*256 + gr*16;

    #pragma unroll
    for (int j = 0; j < 8; j++)
        CP_ASYNC16(bdst0 + j*4096u, bsrc0 + (size_t)j*4096);
    CP_COMMIT();

    // ---- per-lane ldmatrix address components ----
    const int lr  = lane & 7;
    const int l8  = (lane >> 3) & 1;
    const int l16 = (lane >> 4) & 1;
    const uint32_t aBase = sb + (uint32_t)(wm*32 + lr + l8*8) * 256;
    const uint32_t kaddA = (uint32_t)(l16 * 16);
    const uint32_t bBase = sb + SMEM_A_BYTES + (uint32_t)(wn*64 + l16*8 + lr) * 256;
    const uint32_t kaddB = (uint32_t)(l8 * 16);
    const uint32_t lXor  = (uint32_t)(lr * 16);

    float acc[64];
    #pragma unroll
    for (int i = 0; i < 64; i++) acc[i] = 0.f;

    // per-thread top-5 packed (score|code), per s-slot (4 slots)
    uint32_t t1[4], t2[4], t3[4], t4[4], t5[4];
    #pragma unroll
    for (int s = 0; s < 4; s++) { t1[s]=t2[s]=t3[s]=t4[s]=t5[s]=0u; }

    #pragma unroll 1
    for (int nt = 0; nt < 8; nt++) {
        CP_WAIT0();
        __syncthreads();

        if (nt + 1 < 8) {
            uint32_t dst = bdst0 + (uint32_t)((nt + 1) & 1)*SMEM_B_STAGE;
            const char* src = bsrc0 + (size_t)(nt + 1)*32768;
            #pragma unroll
            for (int j = 0; j < 8; j++)
                CP_ASYNC16(dst + j*4096u, src + (size_t)j*4096);
            CP_COMMIT();
        }

        // ---- compute this N-tile: 8 k32-steps ----
        {
            const uint32_t bufB = (uint32_t)(nt & 1)*SMEM_B_STAGE;
            #pragma unroll
            for (int kk = 0; kk < 8; kk++) {
                uint32_t kb = (uint32_t)(kk*32);
                uint32_t aAddr = aBase + ((kb + kaddA) ^ lXor);
                uint32_t a0[4], a1[4];
                LDSM4(a0[0], a0[1], a0[2], a0[3], aAddr);
                LDSM4(a1[0], a1[1], a1[2], a1[3], aAddr + 4096);

                uint32_t bAddr = bBase + bufB + ((kb + kaddB) ^ lXor);
                #pragma unroll
                for (int gb = 0; gb < 2; gb++) {
                    uint32_t bf[8];
                    LDSM4(bf[0], bf[1], bf[2], bf[3], bAddr + (uint32_t)(2*gb)*4096);
                    LDSM4(bf[4], bf[5], bf[6], bf[7], bAddr + (uint32_t)(2*gb+1)*4096);
                    #pragma unroll
                    for (int tt = 0; tt < 4; tt++) {
                        int t8 = gb*4 + tt;
                        uint32_t b0 = bf[(tt >> 1)*4 + (tt & 1)*2 + 0];
                        uint32_t b1 = bf[(tt >> 1)*4 + (tt & 1)*2 + 1];
                        MMAF8(&acc[t8*4],      a0[0], a0[1], a0[2], a0[3], b0, b1);
                        MMAF8(&acc[32 + t8*4], a1[0], a1[1], a1[2], a1[3], b0, b1);
                    }
                }
            }
        }

        // ---- fold this N-tile into per-thread top-5, reset acc ----
        {
            int cBase = nt*128 + wn*64 + (lane & 3)*2;
            #pragma unroll
            for (int mt = 0; mt < 2; mt++) {
                #pragma unroll
                for (int rg = 0; rg < 2; rg++) {
                    int s = mt*2 + rg;
                    #pragma unroll
                    for (int t8 = 0; t8 < 8; t8++) {
                        #pragma unroll
                        for (int e = 0; e < 2; e++) {
                            uint32_t u = pack_sc(acc[mt*32 + t8*4 + rg*2 + e],
                                                 cBase + t8*8 + e);
                            if (u > t1[s])      { t5[s]=t4[s]; t4[s]=t3[s]; t3[s]=t2[s]; t2[s]=t1[s]; t1[s]=u; }
                            else if (u > t2[s]) { t5[s]=t4[s]; t4[s]=t3[s]; t3[s]=t2[s]; t2[s]=u; }
                            else if (u > t3[s]) { t5[s]=t4[s]; t4[s]=t3[s]; t3[s]=u; }
                            else if (u > t4[s]) { t5[s]=t4[s]; t4[s]=u; }
                            else if (u > t5[s]) { t5[s]=u; }
                        }
                    }
                }
            }
            #pragma unroll
            for (int i = 0; i < 64; i++) acc[i] = 0.f;
        }
    }

    // ---- dump per-thread top-5 to smem, merge to token top-10 ----
    __syncthreads();
    uint32_t* red = (uint32_t*)sm;               // [128 tok][8 q][5]
    {
        int q = wn*4 + (lane & 3);
        int row = lane >> 2;
        #pragma unroll
        for (int mt = 0; mt < 2; mt++)
            #pragma unroll
            for (int rg = 0; rg < 2; rg++) {
                int s  = mt*2 + rg;
                int tl = wm*32 + mt*16 + rg*8 + row;
                uint32_t* e = red + (tl*8 + q)*5;
                e[0]=t1[s]; e[1]=t2[s]; e[2]=t3[s]; e[3]=t4[s]; e[4]=t5[s];
            }
    }
    __syncthreads();
    if (tid < 128) {
        uint32_t top[NCAND];
        #pragma unroll
        for (int j = 0; j < NCAND; j++) top[j] = 0u;
        const uint32_t* e = red + tid*40;
        #pragma unroll 4
        for (int j = 0; j < 40; j++) {
            uint32_t u = e[j];
            if (u > top[NCAND-1]) {
                top[NCAND-1] = u;
                #pragma unroll
                for (int t = NCAND-1; t > 0; t--) {
                    uint32_t hi2 = top[t-1], lo2 = top[t];
                    top[t-1] = max(hi2, lo2);
                    top[t]   = min(hi2, lo2);
                }
            }
        }
        int token = mBase + tid;
        #pragma unroll
        for (int j = 0; j < NCAND; j++)
            g_cand[token*NCAND + j] = (int)(top[j] & 1023u);
    }
}

// ============================================================
// fp32 rescore of 10 candidates + gather z_q + loss + counts
// one warp per token
// ============================================================
__global__ void k_fin(const float* __restrict__ z, const float* __restrict__ w,
                      float* __restrict__ out) {
    int wp = threadIdx.x >> 5, lane = threadIdx.x & 31;
    int token = blockIdx.x*8 + wp;

    int cand[NCAND];
    #pragma unroll
    for (int q = 0; q < NCAND; q++) cand[q] = g_cand[token*NCAND + q];

    const float4* zz = (const float4*)(z + (size_t)token*DIM);
    float4 zv[2];
    float d[NCAND];
    #pragma unroll
    for (int q = 0; q < NCAND; q++) d[q] = 0.f;
    #pragma unroll
    for (int rr = 0; rr < 2; rr++) {
        int j = lane + rr*32;
        zv[rr] = zz[j];
        #pragma unroll
        for (int q = 0; q < NCAND; q++) {
            float4 a = ((const float4*)(g_cn + (size_t)cand[q]*DIM))[j];
            d[q] += zv[rr].x*a.x + zv[rr].y*a.y + zv[rr].z*a.z + zv[rr].w*a.w;
        }
    }
    #pragma unroll
    for (int o = 16; o > 0; o >>= 1)
        #pragma unroll
        for (int q = 0; q < NCAND; q++)
            d[q] += __shfl_xor_sync(0xffffffffu, d[q], o);

    float bd = -3.4e38f; int win = 0x7fffffff;
    #pragma unroll
    for (int q = 0; q < NCAND; q++)
        if (d[q] > bd || (d[q] == bd && cand[q] < win)) { bd = d[q]; win = cand[q]; }

    const float4* e  = (const float4*)(w + (size_t)win*DIM);
    float4*       o4 = (float4*)(out + (size_t)token*DIM);
    float s = 0.f;
    #pragma unroll
    for (int rr = 0; rr < 2; rr++) {
        int j = lane + rr*32;
        float4 ev = e[j];
        o4[j] = ev;
        float dx = ev.x - zv[rr].x, dy = ev.y - zv[rr].y;
        float dz = ev.z - zv[rr].z, dw = ev.w - zv[rr].w;
        s += dx*dx + dy*dy + dz*dz + dw*dw;
    }
    #pragma unroll
    for (int o = 16; o > 0; o >>= 1) s += __shfl_xor_sync(0xffffffffu, s, o);
    if (lane == 0) {
        out[ND + 2 + token] = (float)win;
        atomicAdd(&g_counts[win], 1u);
    }
    __shared__ float ps[8];
    if (lane == 0) ps[wp] = s;
    __syncthreads();
    if (threadIdx.x == 0) {
        float tot = 0.f;
        #pragma unroll
        for (int i = 0; i < 8; i++) tot += ps[i];
        atomicAdd(&g_sumsq, (double)tot);
    }
}

// ============================================================
__global__ void k_final(float* __restrict__ out) {
    int t = threadIdx.x;                         // 1024 threads
    float p    = (float)g_counts[t] / (float)NTOK;
    float term = p * logf(p + 1e-10f);
    #pragma unroll
    for (int o = 16; o > 0; o >>= 1) term += __shfl_xor_sync(0xffffffffu, term, o);
    __shared__ float ws[32];
    if ((t & 31) == 0) ws[t >> 5] = term;
    __syncthreads();
    if (t < 32) {
        float v = ws[t];
        #pragma unroll
        for (int o = 16; o > 0; o >>= 1) v += __shfl_xor_sync(0xffffffffu, v, o);
        if (t == 0) {
            out[ND]     = (float)(1.25 * (g_sumsq / (double)ND));
            out[ND + 1] = expf(-v);
        }
    }
}

// ============================================================
extern "C" void kernel_launch(void* const* d_in, const int* in_sizes, int n_in,
                              void* d_out, int out_size) {
    const float* z = (const float*)d_in[0];      // [131072, 256]
    const float* w = (const float*)d_in[1];      // [1024, 256]
    float* out = (float*)d_out;

    cudaFuncSetAttribute(k_gemm, cudaFuncAttributeMaxDynamicSharedMemorySize, SMEM_TOTAL);

    k_init  <<<1, 1024>>>();
    k_norm  <<<NCODE, 64>>>(w);
    k_quantc<<<NCODE, 64>>>();
    k_gemm  <<<NTOK/128, 256, SMEM_TOTAL>>>(z);
    k_fin   <<<NTOK/8, 256>>>(z, w, out);
    k_final <<<1, 1024>>>(out);
}

// round 12
// speedup vs baseline: 1.5695x; 1.2370x over previous
#include <cuda_runtime.h>
#include <cuda_bf16.h>
#include <math.h>
#include <stdint.h>

#define NTOK   131072
#define DIM    256
#define NCODE  1024
#define ND     (NTOK*DIM)

// smem: A = 128 tok x 256 fp8 = 32KB ; B = 2 x (128 codes x 256 fp8) = 64KB
#define SMEM_A_BYTES   32768
#define SMEM_B_STAGE   32768
#define SMEM_TOTAL     (SMEM_A_BYTES + 2*SMEM_B_STAGE)   // 98304

#define NCAND  8
#define BIAS   134217728.0f   // 2^27 > max |score| 448*448*256 ~ 5.1e7

// ---------------- persistent device scratch ----------------
__device__ float          g_cn[NCODE*DIM];      // normalized codebook fp32
__device__ uint8_t        g_cb_f8[NCODE*DIM];   // e4m3 codebook (global scale)
__device__ unsigned int   g_cmax;               // max |cn| as float bits
__device__ int            g_cand[NTOK*NCAND];   // top-8 candidate codes per token
__device__ unsigned int   g_counts[NCODE];
__device__ double         g_sumsq;

__device__ __forceinline__ uint32_t smem_u32(const void* p) {
    uint32_t a;
    asm("{ .reg .u64 t; cvta.to.shared.u64 t, %1; cvt.u32.u64 %0, t; }" : "=r"(a) : "l"(p));
    return a;
}

#define LDSM4(r0,r1,r2,r3,a) \
    asm volatile("ldmatrix.sync.aligned.m8n8.x4.shared.b16 {%0,%1,%2,%3}, [%4];" \
        : "=r"(r0),"=r"(r1),"=r"(r2),"=r"(r3) : "r"(a))

#define MMAF8(d,a0,a1,a2,a3,b0,b1) \
    asm volatile("mma.sync.aligned.m16n8k32.row.col.f32.e4m3.e4m3.f32 " \
        "{%0,%1,%2,%3},{%4,%5,%6,%7},{%8,%9},{%0,%1,%2,%3};" \
        : "+f"((d)[0]),"+f"((d)[1]),"+f"((d)[2]),"+f"((d)[3]) \
        : "r"(a0),"r"(a1),"r"(a2),"r"(a3),"r"(b0),"r"(b1))

#define CP_ASYNC16(dst, src) \
    asm volatile("cp.async.cg.shared.global [%0], [%1], 16;" :: "r"(dst), "l"(src))
#define CP_COMMIT() asm volatile("cp.async.commit_group;" ::: "memory")
#define CP_WAIT0()  asm volatile("cp.async.wait_group 0;"  ::: "memory")

// pack 4 scaled floats into 4 e4m3 bytes (a in low byte)
__device__ __forceinline__ uint32_t pack4_e4m3(float a, float b, float c, float d, float s) {
    uint16_t lo, hi;
    float a_s = a*s, b_s = b*s, c_s = c*s, d_s = d*s;
    asm("cvt.rn.satfinite.e4m3x2.f32 %0, %1, %2;" : "=h"(lo) : "f"(b_s), "f"(a_s));
    asm("cvt.rn.satfinite.e4m3x2.f32 %0, %1, %2;" : "=h"(hi) : "f"(d_s), "f"(c_s));
    return (uint32_t)lo | ((uint32_t)hi << 16);
}

// ============================================================
__global__ void k_init() {
    int t = threadIdx.x;
    if (t < NCODE) g_counts[t] = 0u;
    if (t == 0) { g_sumsq = 0.0; g_cmax = 0u; }
}

// ============================================================
__global__ void k_norm(const float* __restrict__ w) {
    int row = blockIdx.x;
    int t   = threadIdx.x;                       // 64 threads
    float4 v = ((const float4*)(w + row*DIM))[t];
    float s  = v.x*v.x + v.y*v.y + v.z*v.z + v.w*v.w;
    #pragma unroll
    for (int o = 16; o > 0; o >>= 1) s += __shfl_xor_sync(0xffffffffu, s, o);
    __shared__ float ss[2];
    if ((t & 31) == 0) ss[t >> 5] = s;
    __syncthreads();
    float n = sqrtf(ss[0] + ss[1]);
    float r = 1.0f / fmaxf(n, 1e-12f);
    float c[4] = { v.x*r, v.y*r, v.z*r, v.w*r };
    ((float4*)(g_cn + row*DIM))[t] = make_float4(c[0], c[1], c[2], c[3]);
    float am = fmaxf(fmaxf(fabsf(c[0]), fabsf(c[1])), fmaxf(fabsf(c[2]), fabsf(c[3])));
    #pragma unroll
    for (int o = 16; o > 0; o >>= 1) am = fmaxf(am, __shfl_xor_sync(0xffffffffu, am, o));
    if ((t & 31) == 0) atomicMax(&g_cmax, __float_as_uint(am));
}

// ============================================================
__global__ void k_quantc() {
    int row = blockIdx.x, t = threadIdx.x;       // 64 threads
    float cmax = __uint_as_float(g_cmax);
    float s    = (cmax > 0.f) ? 448.0f / cmax : 0.f;
    float4 v = ((const float4*)(g_cn + row*DIM))[t];
    ((uint32_t*)(g_cb_f8 + row*DIM))[t] = pack4_e4m3(v.x, v.y, v.z, v.w, s);
}

// ============================================================
// fp8 e4m3 mma.sync GEMM, mt-split (acc[32], no spills),
// bias-positive packed fold: 1 LOP3 + exact branchless depth-4
// chain per value -> thread top-4 (over its 128 codes/token) ->
// token top-8. CTA: 128 tokens, 8 warps (4m x 2n).
// ============================================================
__global__ void __launch_bounds__(256, 2)
k_gemm(const float* __restrict__ z) {
    extern __shared__ char sm[];
    char* As = sm;
    const uint32_t sb = smem_u32(sm);

    const int tid  = threadIdx.x;
    const int wid  = tid >> 5, lane = tid & 31;
    const int wm   = wid & 3,  wn   = wid >> 2;
    const int mBase = blockIdx.x * 128;

    // ---- A fill: per-token max-abs scale, quantize to e4m3, swizzled ----
    {
        #pragma unroll 1
        for (int i = 0; i < 16; i++) {
            int tok = wid*16 + i;
            const float4* zrow = (const float4*)(z + (size_t)(mBase + tok)*DIM);
            float4 va = zrow[lane];
            float4 vb = zrow[lane + 32];
            float m = fmaxf(fmaxf(fabsf(va.x), fabsf(va.y)), fmaxf(fabsf(va.z), fabsf(va.w)));
            m = fmaxf(m, fmaxf(fmaxf(fabsf(vb.x), fabsf(vb.y)), fmaxf(fabsf(vb.z), fabsf(vb.w))));
            #pragma unroll
            for (int o = 16; o > 0; o >>= 1) m = fmaxf(m, __shfl_xor_sync(0xffffffffu, m, o));
            float s = (m > 0.f) ? 448.0f / m : 0.f;
            uint32_t u0 = pack4_e4m3(va.x, va.y, va.z, va.w, s);
            uint32_t u1 = pack4_e4m3(vb.x, vb.y, vb.z, vb.w, s);
            int base = tok*256, xo = (tok & 7)*16;
            *(uint32_t*)(As + base + ((lane*4)       ^ xo)) = u0;
            *(uint32_t*)(As + base + ((128 + lane*4) ^ xo)) = u1;
        }
    }

    // ---- B cp.async addressing: stage = 128 rows x 256B, 16B chunks ----
    const int r0 = tid >> 4, gr = tid & 15;
    const uint32_t bdst0 = sb + SMEM_A_BYTES +
        (uint32_t)(r0*256 + ((gr*16) ^ ((r0 & 7)*16)));
    const char* bsrc0 = (const char*)g_cb_f8 + (size_t)r0*256 + gr*16;

    #pragma unroll
    for (int j = 0; j < 8; j++)
        CP_ASYNC16(bdst0 + j*4096u, bsrc0 + (size_t)j*4096);
    CP_COMMIT();

    // ---- per-lane ldmatrix address components ----
    const int lr  = lane & 7;
    const int l8  = (lane >> 3) & 1;
    const int l16 = (lane >> 4) & 1;
    const uint32_t aBase = sb + (uint32_t)(wm*32 + lr + l8*8) * 256;
    const uint32_t kaddA = (uint32_t)(l16 * 16);
    const uint32_t bBase = sb + SMEM_A_BYTES + (uint32_t)(wn*64 + l16*8 + lr) * 256;
    const uint32_t kaddB = (uint32_t)(l8 * 16);
    const uint32_t lXor  = (uint32_t)(lr * 16);

    // per-(token-row slot) exact top-4 chains of packed entries:
    // entry = (score_bits & ~0x7F) | (nt<<4) | (t8<<1) | e
    uint32_t c1[4], c2[4], c3[4], c4[4];
    #pragma unroll
    for (int s = 0; s < 4; s++) { c1[s]=c2[s]=c3[s]=c4[s]=0u; }

    #pragma unroll 1
    for (int nt = 0; nt < 8; nt++) {
        CP_WAIT0();
        __syncthreads();

        if (nt + 1 < 8) {
            uint32_t dst = bdst0 + (uint32_t)((nt + 1) & 1)*SMEM_B_STAGE;
            const char* src = bsrc0 + (size_t)(nt + 1)*32768;
            #pragma unroll
            for (int j = 0; j < 8; j++)
                CP_ASYNC16(dst + j*4096u, src + (size_t)j*4096);
            CP_COMMIT();
        }

        const uint32_t bufB   = (uint32_t)(nt & 1)*SMEM_B_STAGE;
        const uint32_t ntbits = (uint32_t)(nt << 4);

        // ---- two m-half passes: acc[32] each, fold between ----
        #pragma unroll
        for (int mt = 0; mt < 2; mt++) {
            float acc[32];
            #pragma unroll
            for (int i = 0; i < 32; i++) acc[i] = BIAS;

            #pragma unroll
            for (int kk = 0; kk < 8; kk++) {
                uint32_t kb = (uint32_t)(kk*32);
                uint32_t aAddr = aBase + (uint32_t)(mt*4096) + ((kb + kaddA) ^ lXor);
                uint32_t a0[4];
                LDSM4(a0[0], a0[1], a0[2], a0[3], aAddr);

                uint32_t bAddr = bBase + bufB + ((kb + kaddB) ^ lXor);
                #pragma unroll
                for (int gb = 0; gb < 2; gb++) {
                    uint32_t bf[8];
                    LDSM4(bf[0], bf[1], bf[2], bf[3], bAddr + (uint32_t)(2*gb)*4096);
                    LDSM4(bf[4], bf[5], bf[6], bf[7], bAddr + (uint32_t)(2*gb+1)*4096);
                    #pragma unroll
                    for (int tt = 0; tt < 4; tt++) {
                        int t8 = gb*4 + tt;
                        uint32_t b0 = bf[(tt >> 1)*4 + (tt & 1)*2 + 0];
                        uint32_t b1 = bf[(tt >> 1)*4 + (tt & 1)*2 + 1];
                        MMAF8(&acc[t8*4], a0[0], a0[1], a0[2], a0[3], b0, b1);
                    }
                }
            }

            // ---- fold this half: 32 values -> 2 slot chains ----
            #pragma unroll
            for (int rg = 0; rg < 2; rg++) {
                const int s = mt*2 + rg;
                #pragma unroll
                for (int t8 = 0; t8 < 8; t8++) {
                    #pragma unroll
                    for (int e = 0; e < 2; e++) {
                        // positive floats: uint order == float order
                        uint32_t u = (__float_as_uint(acc[t8*4 + rg*2 + e]) & 0xFFFFFF80u)
                                     | (ntbits + (uint32_t)(t8*2 + e));
                        // exact branchless depth-4 insert
                        uint32_t d1 = min(c1[s], u);  c1[s] = max(c1[s], u);
                        uint32_t d2 = min(c2[s], d1); c2[s] = max(c2[s], d1);
                        uint32_t d3 = min(c3[s], d2); c3[s] = max(c3[s], d2);
                        c4[s] = max(c4[s], d3);
                    }
                }
            }
        }
    }

    // ---- dump per-thread top-4 to smem, merge to token top-8 ----
    __syncthreads();
    uint32_t* red = (uint32_t*)sm;               // [128 tok][8 q][4]
    {
        int q = wn*4 + (lane & 3);
        int row = lane >> 2;
        #pragma unroll
        for (int mt = 0; mt < 2; mt++)
            #pragma unroll
            for (int rg = 0; rg < 2; rg++) {
                int s  = mt*2 + rg;
                int tl = wm*32 + mt*16 + rg*8 + row;
                uint32_t* e = red + (tl*8 + q)*4;
                e[0]=c1[s]; e[1]=c2[s]; e[2]=c3[s]; e[3]=c4[s];
            }
    }
    __syncthreads();
    if (tid < 128) {
        uint32_t top[NCAND];
        int      cod[NCAND];
        #pragma unroll
        for (int j = 0; j < NCAND; j++) { top[j] = 0u; cod[j] = 0; }
        const uint32_t* e = red + tid*32;
        #pragma unroll 4
        for (int j = 0; j < 32; j++) {
            uint32_t u = e[j];
            if (u > top[NCAND-1]) {
                int q = (j >> 2);                // entry's owner q = wn*4+(lane&3)
                int code = (int)(((u >> 4) & 7u)*128u + (u & 15u)*0u)  // placeholder
                         ;
                // decode: nt=[6:4], t8=[3:1], e=[0]
                int nt_ = (int)((u >> 4) & 7u);
                int t8_ = (int)((u >> 1) & 7u);
                int e_  = (int)(u & 1u);
                code = nt_*128 + (q >> 2)*64 + t8_*8 + (q & 3)*2 + e_;
                top[NCAND-1] = u; cod[NCAND-1] = code;
                #pragma unroll
                for (int t = NCAND-1; t > 0; t--) {
                    if (top[t] > top[t-1]) {
                        uint32_t tu = top[t-1]; top[t-1] = top[t]; top[t] = tu;
                        int tc = cod[t-1]; cod[t-1] = cod[t]; cod[t] = tc;
                    }
                }
            }
        }
        int token = mBase + tid;
        #pragma unroll
        for (int j = 0; j < NCAND; j++)
            g_cand[token*NCAND + j] = cod[j];
    }
}

// ============================================================
// fp32 rescore of 8 candidates + gather z_q + loss + counts
// one warp per token
// ============================================================
__global__ void k_fin(const float* __restrict__ z, const float* __restrict__ w,
                      float* __restrict__ out) {
    int wp = threadIdx.x >> 5, lane = threadIdx.x & 31;
    int token = blockIdx.x*8 + wp;

    int cand[NCAND];
    #pragma unroll
    for (int q = 0; q < NCAND; q++) cand[q] = g_cand[token*NCAND + q];

    const float4* zz = (const float4*)(z + (size_t)token*DIM);
    float4 zv[2];
    float d[NCAND];
    #pragma unroll
    for (int q = 0; q < NCAND; q++) d[q] = 0.f;
    #pragma unroll
    for (int rr = 0; rr < 2; rr++) {
        int j = lane + rr*32;
        zv[rr] = zz[j];
        #pragma unroll
        for (int q = 0; q < NCAND; q++) {
            float4 a = ((const float4*)(g_cn + (size_t)cand[q]*DIM))[j];
            d[q] += zv[rr].x*a.x + zv[rr].y*a.y + zv[rr].z*a.z + zv[rr].w*a.w;
        }
    }
    #pragma unroll
    for (int o = 16; o > 0; o >>= 1)
        #pragma unroll
        for (int q = 0; q < NCAND; q++)
            d[q] += __shfl_xor_sync(0xffffffffu, d[q], o);

    float bd = -3.4e38f; int win = 0x7fffffff;
    #pragma unroll
    for (int q = 0; q < NCAND; q++)
        if (d[q] > bd || (d[q] == bd && cand[q] < win)) { bd = d[q]; win = cand[q]; }

    const float4* e  = (const float4*)(w + (size_t)win*DIM);
    float4*       o4 = (float4*)(out + (size_t)token*DIM);
    float s = 0.f;
    #pragma unroll
    for (int rr = 0; rr < 2; rr++) {
        int j = lane + rr*32;
        float4 ev = e[j];
        o4[j] = ev;
        float dx = ev.x - zv[rr].x, dy = ev.y - zv[rr].y;
        float dz = ev.z - zv[rr].z, dw = ev.w - zv[rr].w;
        s += dx*dx + dy*dy + dz*dz + dw*dw;
    }
    #pragma unroll
    for (int o = 16; o > 0; o >>= 1) s += __shfl_xor_sync(0xffffffffu, s, o);
    if (lane == 0) {
        out[ND + 2 + token] = (float)win;
        atomicAdd(&g_counts[win], 1u);
    }
    __shared__ float ps[8];
    if (lane == 0) ps[wp] = s;
    __syncthreads();
    if (threadIdx.x == 0) {
        float tot = 0.f;
        #pragma unroll
        for (int i = 0; i < 8; i++) tot += ps[i];
        atomicAdd(&g_sumsq, (double)tot);
    }
}

// ============================================================
__global__ void k_final(float* __restrict__ out) {
    int t = threadIdx.x;                         // 1024 threads
    float p    = (float)g_counts[t] / (float)NTOK;
    float term = p * logf(p + 1e-10f);
    #pragma unroll
    for (int o = 16; o > 0; o >>= 1) term += __shfl_xor_sync(0xffffffffu, term, o);
    __shared__ float ws[32];
    if ((t & 31) == 0) ws[t >> 5] = term;
    __syncthreads();
    if (t < 32) {
        float v = ws[t];
        #pragma unroll
        for (int o = 16; o > 0; o >>= 1) v += __shfl_xor_sync(0xffffffffu, v, o);
        if (t == 0) {
            out[ND]     = (float)(1.25 * (g_sumsq / (double)ND));
            out[ND + 1] = expf(-v);
        }
    }
}

// ============================================================
extern "C" void kernel_launch(void* const* d_in, const int* in_sizes, int n_in,
                              void* d_out, int out_size) {
    const float* z = (const float*)d_in[0];      // [131072, 256]
    const float* w = (const float*)d_in[1];      // [1024, 256]
    float* out = (float*)d_out;

    cudaFuncSetAttribute(k_gemm, cudaFuncAttributeMaxDynamicSharedMemorySize, SMEM_TOTAL);

    k_init  <<<1, 1024>>>();
    k_norm  <<<NCODE, 64>>>(w);
    k_quantc<<<NCODE, 64>>>();
    k_gemm  <<<NTOK/128, 256, SMEM_TOTAL>>>(z);
    k_fin   <<<NTOK/8, 256>>>(z, w, out);
    k_final <<<1, 1024>>>(out);
}